// round 8
// baseline (speedup 1.0000x reference)
#include <cuda_runtime.h>
#include <math.h>

// ---------------------------------------------------------------------------
// AcousticGuitarPoC R8: K1a (params + pre-LP) -> K1b (full-chip doubling FIR)
// -> K2 (uniform 128-round serial KS + post-LP) -> bodyA/B/C (BL=64).
// B=8, N=32768. 6 kernel launches.
// ---------------------------------------------------------------------------

#define FS_F   44100.0f
#define PI_F   3.14159265358979323846f
#define NB     24
#define NSMP   32768
#define BATCH  8
#define NTH    256      // K1a/K2 threads
#define LCH    128      // LP chunk length (256*128 = 32768)
#define KSL    1024     // KS ring (power of 2)
#define BL     64       // body chunk length
#define BC     512      // body chunk count (512*64 = 32768)
#define NLVL   9        // log2(BC) scan levels

#define SIDX(n) ((n) + ((n) >> 7))          // skewed signal index
#define SIGSZ   (NSMP + (NSMP >> 7))        // 33024 floats

struct BParams {
    float mpre, scpre, mpost, scpost;
    int   lag;
    float serc[9];      // serial ring taps at lag..lag+8 (zero-padded)
    float xfc[15];      // doubling FIR taps (zero-padded)
    int   xfo[15];      // FIR offsets (padded entries -> 1, coef 0)
};

__device__ BParams d_bp[BATCH];
__device__ float  d_xlp[BATCH * NSMP];        // pre-LP'd signal
__device__ float  d_g[BATCH * NSMP];          // doubling-FIR output
__device__ float  d_bA1[NB], d_bA2[NB], d_bB0[NB];
__device__ float  d_Pl[NB][NLVL][4];          // M^(64*2^j), double-computed
__device__ float  d_scr[BATCH * NSMP];        // string output for body stage
__device__ float2 d_carry[BATCH][BC][NB];
__device__ float2 d_initS[BATCH][BC][NB];

__device__ __forceinline__ float sigm(float x) { return 1.f / (1.f + expf(-x)); }
__device__ __forceinline__ float clampf(float x, float lo, float hi) {
    return fminf(fmaxf(x, lo), hi);
}

__device__ __forceinline__ void mlp_eval(float p,
    const float* __restrict__ w1, const float* __restrict__ b1,
    const float* __restrict__ w2, const float* __restrict__ b2,
    float& lc, float& lm, float& lp)
{
    float m0 = b2[0], m1 = b2[1], m2 = b2[2];
    #pragma unroll
    for (int j = 0; j < 16; j++) {
        float h = fmaxf(fmaf(p, w1[j], b1[j]), 0.f);
        m0 = fmaf(h, w2[j],      m0);
        m1 = fmaf(h, w2[16 + j], m1);
        m2 = fmaf(h, w2[32 + j], m2);
    }
    lc = clampf(m0, -2.0f, 2.5f);
    lm = clampf(m1, -2.5f, 0.0f);
    lp = clampf(m2, -4.0f, 4.0f);
}

// In-place one-pole LP on the skewed signal (proven R7 version).
__device__ void lp_inplace(float* sig, float* ws, float m, float sc, int tid)
{
    int lane = tid & 31, wid = tid >> 5;
    float* x = sig + tid * (LCH + 1);

    float e = 0.f;
    #pragma unroll 8
    for (int k = 0; k < LCH; k++) e = fmaf(m, e, sc * x[k]);

    float f128 = m;
    #pragma unroll
    for (int i = 0; i < 7; i++) f128 *= f128;

    float f = f128;
    #pragma unroll
    for (int ofs = 1; ofs < 32; ofs <<= 1) {
        float v = __shfl_up_sync(0xffffffffu, e, ofs);
        if (lane >= ofs) e = fmaf(f, v, e);
        f *= f;
    }

    if (lane == 31) ws[wid] = e;
    __syncthreads();
    if (wid == 0 && lane < 8) {
        float t = ws[lane];
        float g = f;
        #pragma unroll
        for (int ofs = 1; ofs < 8; ofs <<= 1) {
            float v = __shfl_up_sync(0x000000ffu, t, ofs);
            if (lane >= ofs) t = fmaf(g, v, t);
            g *= g;
        }
        ws[lane] = t;
    }
    __syncthreads();

    float carry = (wid > 0) ? ws[wid - 1] : 0.f;
    float lmul = exp2f((float)(lane + 1) * log2f(f128));
    float Y = fmaf(lmul, carry, e);
    float yp = __shfl_up_sync(0xffffffffu, Y, 1);
    if (lane == 0) yp = carry;
    if (tid == 0)  yp = 0.f;

    #pragma unroll 8
    for (int k = 0; k < LCH; k++) { yp = fmaf(m, yp, sc * x[k]); x[k] = yp; }
    __syncthreads();
}

// ---------------------------------------------------------------------------
// K1a: per-batch params + band setup + pre one-pole LP. One block per batch.
// ---------------------------------------------------------------------------
__global__ void k1a_kernel(const float* __restrict__ exc,
                           const float* __restrict__ pitch,
                           const float* __restrict__ w1,
                           const float* __restrict__ b1,
                           const float* __restrict__ w2,
                           const float* __restrict__ b2,
                           const float* __restrict__ egain,
                           float* out_tail, int write_scalars)
{
    extern __shared__ float sm[];
    float* sig  = sm;              // [SIGSZ]
    float* scan = sm + SIGSZ;      // [NTH]

    __shared__ float s_lc[BATCH], s_lm[BATCH], s_lp[BATCH];
    __shared__ float s_mpre, s_scpre;
    int b = blockIdx.x, tid = threadIdx.x;

    if (tid == 0) {
        float p = pitch[b];
        float lc, lm, lp;
        mlp_eval(p, w1, b1, w2, b2, lc, lm, lp);

        float g = 0.999f * sigm(lc);
        float s = sigm(lm);
        float gs  = g * s;
        float g1s = g * (1.f - s);

        BParams P;
        float f0    = fmaxf(p, 60.f);
        float mult  = clampf(2.f + 6.f * (f0 - 60.f) / 600.f, 2.f, 8.f);
        float cut   = fminf(2.f * PI_F * f0 * mult / FS_F, PI_F * 0.9f);
        float alpha = 1.f - expf(-cut);
        P.mpre  = 1.f - alpha;
        P.scpre = alpha * egain[0];
        s_mpre = P.mpre; s_scpre = P.scpre;

        float cutp = fminf(PI_F * sigm(lp), PI_F * 0.99f);
        float ap   = 1.f - expf(-cutp);
        P.mpost  = 1.f - ap;
        P.scpost = ap;

        float D  = clampf(FS_F / f0, 2.f, 735.f);
        float Df = floorf(D);
        int   Di = (int)Df;
        float fr = D - Df;

        float t1[3], t2[5], t3[7], t4[9];
        t1[0] = g1s * (1.f - fr);
        t1[1] = g1s * fr + gs * (1.f - fr);
        t1[2] = gs * fr;
        for (int k = 0; k < 5; k++) t2[k] = 0.f;
        for (int i = 0; i < 3; i++)
            for (int j = 0; j < 3; j++) t2[i + j] = fmaf(t1[i], t1[j], t2[i + j]);
        for (int k = 0; k < 7; k++) t3[k] = 0.f;
        for (int i = 0; i < 3; i++)
            for (int j = 0; j < 5; j++) t3[i + j] = fmaf(t1[i], t2[j], t3[i + j]);
        for (int k = 0; k < 9; k++) t4[k] = 0.f;
        for (int i = 0; i < 5; i++)
            for (int j = 0; j < 5; j++) t4[i + j] = fmaf(t2[i], t2[j], t4[i + j]);

        for (int k = 0; k < 9;  k++) P.serc[k] = 0.f;
        for (int k = 0; k < 15; k++) { P.xfc[k] = 0.f; P.xfo[k] = 1; }

        if (Di >= 256) {                 // L=0: lag=Di >= Cb=256
            P.lag = Di;
            for (int k = 0; k < 3; k++) P.serc[k] = t1[k];
        } else if (Di >= 128) {          // L=1: lag=2Di >= 256
            P.lag = 2 * Di;
            for (int k = 0; k < 5; k++) P.serc[k] = t2[k];
            for (int k = 0; k < 3; k++) { P.xfc[k] = t1[k]; P.xfo[k] = Di + k; }
        } else {                         // L=2: lag=4Di >= 264 (Di >= 66)
            P.lag = 4 * Di;
            for (int k = 0; k < 9; k++) P.serc[k] = t4[k];
            int q = 0;
            for (int k = 0; k < 3; k++, q++) { P.xfc[q] = t1[k]; P.xfo[q] = Di + k; }
            for (int k = 0; k < 5; k++, q++) { P.xfc[q] = t2[k]; P.xfo[q] = 2 * Di + k; }
            for (int k = 0; k < 7; k++, q++) { P.xfc[q] = t3[k]; P.xfo[q] = 3 * Di + k; }
        }
        d_bp[b] = P;
    }

    if (b == 0) {
        if (tid >= 32 && tid < 32 + BATCH) {
            int bb = tid - 32;
            mlp_eval(pitch[bb], w1, b1, w2, b2, s_lc[bb], s_lm[bb], s_lp[bb]);
        }
        if (tid >= 64 && tid < 64 + NB) {
            int band = tid - 64;
            double fc  = 80.0 * exp(log(100.0) * (double)band / 23.0);
            float  fcf = (float)fc;
            float  w   = 2.f * PI_F * fcf / FS_F;
            float  r   = expf(-PI_F * fcf / (10.f * FS_F));
            float  a1  = -2.f * r * cosf(w);
            float  a2  = r * r;
            d_bA1[band] = a1; d_bA2[band] = a2; d_bB0[band] = 1.f - r;
            // M = [[-a1,-a2],[1,0]]; level powers M^(64*2^j), all in double.
            double ma = -(double)a1, mb = -(double)a2, mc = 1.0, md = 0.0;
            for (int it = 0; it < 6; it++) {          // -> M^64
                double na = ma * ma + mb * mc;
                double nb = ma * mb + mb * md;
                double nc = mc * ma + md * mc;
                double nd = mc * mb + md * md;
                ma = na; mb = nb; mc = nc; md = nd;
            }
            for (int j = 0; j < NLVL; j++) {
                d_Pl[band][j][0] = (float)ma; d_Pl[band][j][1] = (float)mb;
                d_Pl[band][j][2] = (float)mc; d_Pl[band][j][3] = (float)md;
                double na = ma * ma + mb * mc;
                double nb = ma * mb + mb * md;
                double nc = mc * ma + md * mc;
                double nd = mc * mb + md * md;
                ma = na; mb = nb; mc = nc; md = nd;
            }
        }
    }
    __syncthreads();

    if (b == 0 && tid == 0 && write_scalars) {
        float sc = 0.f, smm = 0.f, spp = 0.f;
        for (int i = 0; i < BATCH; i++) { sc += s_lc[i]; smm += s_lm[i]; spp += s_lp[i]; }
        out_tail[0] = sc  / (float)BATCH;
        out_tail[1] = smm / (float)BATCH;
        out_tail[2] = spp / (float)BATCH;
    }

    // load excitation (skewed), pre-LP, write xlp
    const float* xin = exc + b * NSMP;
    for (int i = tid; i < NSMP; i += NTH) sig[SIDX(i)] = xin[i];
    __syncthreads();

    lp_inplace(sig, scan, s_mpre, s_scpre, tid);

    float* xout = d_xlp + b * NSMP;
    for (int i = tid; i < NSMP; i += NTH) xout[i] = sig[SIDX(i)];
}

// ---------------------------------------------------------------------------
// K1b: doubling FIR, full chip. grid (16 segs, BATCH) x 256.
// g[n] = xlp[n] + sum_j xfc[j] * xlp[n - xfo[j]]
// ---------------------------------------------------------------------------
__global__ void k1b_kernel()
{
    int b = blockIdx.y, seg = blockIdx.x, tid = threadIdx.x;
    __shared__ float sc[15];
    __shared__ int   so[15];
    if (tid < 15) { sc[tid] = d_bp[b].xfc[tid]; so[tid] = d_bp[b].xfo[tid]; }
    __syncthreads();

    float c[15]; int o[15];
    #pragma unroll
    for (int j = 0; j < 15; j++) { c[j] = sc[j]; o[j] = so[j]; }

    const float* x = d_xlp + b * NSMP;
    float* g = d_g + b * NSMP;
    #pragma unroll
    for (int s = 0; s < 8; s++) {
        int n = seg * 2048 + s * 256 + tid;
        float acc = x[n];
        #pragma unroll
        for (int j = 0; j < 15; j++) {
            int idx = n - o[j];
            float v = (idx >= 0) ? x[idx] : 0.f;
            acc = fmaf(c[j], v, acc);
        }
        g[n] = acc;
    }
}

// ---------------------------------------------------------------------------
// K2: uniform serial KS (always 128 rounds of 256) + post-LP.
// sig holds g; each slot is read once then overwritten with y.
// ---------------------------------------------------------------------------
__global__ void k2_kernel()
{
    extern __shared__ float sm[];
    float* sig  = sm;              // [SIGSZ] g, becomes y
    float* buf  = sm + SIGSZ;      // [KSL] ring
    float* scan = buf + KSL;       // [NTH]

    int b = blockIdx.x, tid = threadIdx.x;

    __shared__ float s_c[9];
    __shared__ int   s_lag;
    __shared__ float s_mpost, s_scpost;
    if (tid < 9) s_c[tid] = d_bp[b].serc[tid];
    if (tid == 9)  s_lag    = d_bp[b].lag;
    if (tid == 10) s_mpost  = d_bp[b].mpost;
    if (tid == 11) s_scpost = d_bp[b].scpost;

    const float* gin = d_g + b * NSMP;
    for (int i = tid; i < NSMP; i += NTH) sig[SIDX(i)] = gin[i];
    for (int i = tid; i < KSL; i += NTH) buf[i] = 0.f;
    __syncthreads();

    float c0 = s_c[0], c1 = s_c[1], c2 = s_c[2], c3 = s_c[3], c4 = s_c[4],
          c5 = s_c[5], c6 = s_c[6], c7 = s_c[7], c8 = s_c[8];
    int lag = s_lag;

    // negative-time ring slots hold initial zeros (lag+j+pad <= 743 < 1024);
    // intra-round alias impossible: (lag+j-dn) in [1, 998], never 0 mod 1024.
    #pragma unroll 1
    for (int k = 0; k < NSMP / NTH; k++) {
        int n = k * NTH + tid;
        float gv = sig[SIDX(n)];
        int p = n - lag + 2048;
        float fa, fb2;
        fa  = c0 * buf[(p    ) & (KSL - 1)];
        fb2 = c1 * buf[(p - 1) & (KSL - 1)];
        fa  = fmaf(c2, buf[(p - 2) & (KSL - 1)], fa);
        fb2 = fmaf(c3, buf[(p - 3) & (KSL - 1)], fb2);
        fa  = fmaf(c4, buf[(p - 4) & (KSL - 1)], fa);
        fb2 = fmaf(c5, buf[(p - 5) & (KSL - 1)], fb2);
        fa  = fmaf(c6, buf[(p - 6) & (KSL - 1)], fa);
        fb2 = fmaf(c7, buf[(p - 7) & (KSL - 1)], fb2);
        fa  = fmaf(c8, buf[(p - 8) & (KSL - 1)], fa);
        float y = gv + fa + fb2;
        buf[n & (KSL - 1)] = y;
        sig[SIDX(n)] = y;
        __syncthreads();
    }

    lp_inplace(sig, scan, s_mpost, s_scpost, tid);

    float* yout = d_scr + b * NSMP;
    for (int i = tid; i < NSMP; i += NTH) yout[i] = sig[SIDX(i)];
}

// ---------------------------------------------------------------------------
// Body pass A: per (chunk, batch) 1-warp block, lane = band. BL=64.
// ---------------------------------------------------------------------------
__global__ void bodyA_kernel()
{
    __shared__ float shx[BL];
    int b = blockIdx.y, c = blockIdx.x, tid = threadIdx.x;
    const float* x = d_scr + b * NSMP + c * BL;
    for (int i = tid; i < BL; i += 32) shx[i] = x[i];
    __syncthreads();
    if (tid < NB) {
        float a1 = d_bA1[tid], a2 = d_bA2[tid], b0 = d_bB0[tid];
        float y1 = 0.f, y2 = 0.f;
        #pragma unroll 8
        for (int t = 0; t < BL; t++) {
            float u = fmaf(-a2, y2, b0 * shx[t]);
            float y = fmaf(-a1, y1, u);
            y2 = y1; y1 = y;
        }
        d_carry[b][c][tid] = make_float2(y1, y2);
    }
}

// ---------------------------------------------------------------------------
// Body pass B: parallel affine scan of 512 chunk carries (9 exact levels).
// ---------------------------------------------------------------------------
__global__ void bodyB_kernel()
{
    __shared__ float2 s[BC];
    int band = blockIdx.x, b = blockIdx.y, c = threadIdx.x;
    float2 v = d_carry[b][c][band];
    s[c] = v;
    __syncthreads();
    #pragma unroll
    for (int j = 0; j < NLVL; j++) {
        int ofs = 1 << j;
        float q00 = d_Pl[band][j][0], q01 = d_Pl[band][j][1];
        float q10 = d_Pl[band][j][2], q11 = d_Pl[band][j][3];
        float2 pv = (c >= ofs) ? s[c - ofs] : make_float2(0.f, 0.f);
        __syncthreads();
        v.x = fmaf(q00, pv.x, fmaf(q01, pv.y, v.x));
        v.y = fmaf(q10, pv.x, fmaf(q11, pv.y, v.y));
        s[c] = v;
        __syncthreads();
    }
    d_initS[b][c][band] = (c > 0) ? s[c - 1] : make_float2(0.f, 0.f);
}

// ---------------------------------------------------------------------------
// Body pass C: recompute chunks with correct init, weighted band sum.
// ---------------------------------------------------------------------------
__global__ void bodyC_kernel(const float* __restrict__ gains, float* __restrict__ out)
{
    __shared__ float shx[BL];
    __shared__ float tile[BL * 25];
    __shared__ float shg[NB];
    int b = blockIdx.y, c = blockIdx.x, tid = threadIdx.x;
    const float* x = d_scr + b * NSMP + c * BL;
    for (int i = tid; i < BL; i += 32) shx[i] = x[i];
    if (tid < NB) shg[tid] = gains[tid];
    __syncthreads();

    if (tid < NB) {
        float a1 = d_bA1[tid], a2 = d_bA2[tid], b0 = d_bB0[tid];
        float2 s = d_initS[b][c][tid];
        float y1 = s.x, y2 = s.y;
        #pragma unroll 8
        for (int t = 0; t < BL; t++) {
            float u = fmaf(-a2, y2, b0 * shx[t]);
            float y = fmaf(-a1, y1, u);
            tile[t * 25 + tid] = y;
            y2 = y1; y1 = y;
        }
    }
    __syncthreads();

    for (int t = tid; t < BL; t += 32) {
        float acc = 0.f;
        #pragma unroll
        for (int k = 0; k < NB; k++) acc = fmaf(tile[t * 25 + k], shg[k], acc);
        out[b * NSMP + c * BL + t] = acc;
    }
}

// ---------------------------------------------------------------------------
extern "C" void kernel_launch(void* const* d_in, const int* in_sizes, int n_in,
                              void* d_out, int out_size)
{
    const float* exc   = (const float*)d_in[0];   // [8,1,32768]
    const float* pitch = (const float*)d_in[1];   // [8,1]
    const float* w1    = (const float*)d_in[2];   // [16,1]
    const float* b1    = (const float*)d_in[3];   // [16]
    const float* w2    = (const float*)d_in[4];   // [3,16]
    const float* b2    = (const float*)d_in[5];   // [3]
    const float* eg    = (const float*)d_in[6];   // scalar
    const float* bg    = (const float*)d_in[7];   // [1,24]
    float* out = (float*)d_out;

    int wr = (out_size >= BATCH * NSMP + 3) ? 1 : 0;

    const int smem_k1a = (SIGSZ + NTH) * (int)sizeof(float);         // ~130 KB
    const int smem_k2  = (SIGSZ + KSL + NTH) * (int)sizeof(float);   // ~137 KB
    cudaFuncSetAttribute(k1a_kernel,
                         cudaFuncAttributeMaxDynamicSharedMemorySize, smem_k1a);
    cudaFuncSetAttribute(k2_kernel,
                         cudaFuncAttributeMaxDynamicSharedMemorySize, smem_k2);

    k1a_kernel<<<BATCH, NTH, smem_k1a>>>(exc, pitch, w1, b1, w2, b2, eg,
                                         out + BATCH * NSMP, wr);
    k1b_kernel<<<dim3(16, BATCH), NTH>>>();
    k2_kernel<<<BATCH, NTH, smem_k2>>>();
    bodyA_kernel<<<dim3(BC, BATCH), 32>>>();
    bodyB_kernel<<<dim3(NB, BATCH), BC>>>();
    bodyC_kernel<<<dim3(BC, BATCH), 32>>>(bg, out);
}

// round 9
// speedup vs baseline: 1.3616x; 1.3616x over previous
#include <cuda_runtime.h>
#include <math.h>

// ---------------------------------------------------------------------------
// AcousticGuitarPoC R9 = R7 fused kernel (proven 51.7us) + state-space chain
// doubling (A^2) in bodyA/bodyC to halve the serial 2-pole latency chains.
// B=8, N=32768. 4 launches.
// ---------------------------------------------------------------------------

#define FS_F   44100.0f
#define PI_F   3.14159265358979323846f
#define NB     24
#define NSMP   32768
#define BATCH  8
#define NTH    256      // fused-kernel threads
#define LCH    128      // LP chunk length (256*128 = 32768)
#define KSL    1024     // KS ring (power of 2)
#define BL     128      // body chunk length
#define BC     256      // body chunk count (256*128 = 32768)
#define NLVL   8        // log2(BC) scan levels

#define SIDX(n) ((n) + ((n) >> 7))          // skewed signal index
#define SIGSZ   (NSMP + (NSMP >> 7))        // 33024 floats

__device__ float  d_bA1[NB], d_bA2[NB], d_bB0[NB];
__device__ float  d_A2[NB][4];                // A^2 per band (double-computed)
__device__ float  d_Pl[NB][NLVL][4];          // M^(BL*2^j), double-computed
__device__ float  d_scr[BATCH * NSMP];        // string output for body stage
__device__ float2 d_carry[BATCH][BC][NB];     // body zero-init chunk end states
__device__ float2 d_initS[BATCH][BC][NB];     // body corrected chunk init states

__device__ __forceinline__ float sigm(float x) { return 1.f / (1.f + expf(-x)); }
__device__ __forceinline__ float clampf(float x, float lo, float hi) {
    return fminf(fmaxf(x, lo), hi);
}

__device__ __forceinline__ void mlp_eval(float p,
    const float* __restrict__ w1, const float* __restrict__ b1,
    const float* __restrict__ w2, const float* __restrict__ b2,
    float& lc, float& lm, float& lp)
{
    float m0 = b2[0], m1 = b2[1], m2 = b2[2];
    #pragma unroll
    for (int j = 0; j < 16; j++) {
        float h = fmaxf(fmaf(p, w1[j], b1[j]), 0.f);
        m0 = fmaf(h, w2[j],      m0);
        m1 = fmaf(h, w2[16 + j], m1);
        m2 = fmaf(h, w2[32 + j], m2);
    }
    lc = clampf(m0, -2.0f, 2.5f);
    lm = clampf(m1, -2.5f, 0.0f);
    lp = clampf(m2, -4.0f, 4.0f);
}

// In-place one-pole LP on the SKEWED signal (proven R7 version).
__device__ void lp_inplace(float* sig, float* ws, float m, float sc, int tid)
{
    int lane = tid & 31, wid = tid >> 5;
    float* x = sig + tid * (LCH + 1);

    float e = 0.f;
    #pragma unroll 8
    for (int k = 0; k < LCH; k++) e = fmaf(m, e, sc * x[k]);

    float f128 = m;
    #pragma unroll
    for (int i = 0; i < 7; i++) f128 *= f128;

    float f = f128;
    #pragma unroll
    for (int ofs = 1; ofs < 32; ofs <<= 1) {
        float v = __shfl_up_sync(0xffffffffu, e, ofs);
        if (lane >= ofs) e = fmaf(f, v, e);
        f *= f;
    }

    if (lane == 31) ws[wid] = e;
    __syncthreads();
    if (wid == 0 && lane < 8) {
        float t = ws[lane];
        float g = f;
        #pragma unroll
        for (int ofs = 1; ofs < 8; ofs <<= 1) {
            float v = __shfl_up_sync(0x000000ffu, t, ofs);
            if (lane >= ofs) t = fmaf(g, v, t);
            g *= g;
        }
        ws[lane] = t;
    }
    __syncthreads();

    float carry = (wid > 0) ? ws[wid - 1] : 0.f;
    float lmul = exp2f((float)(lane + 1) * log2f(f128));
    float Y = fmaf(lmul, carry, e);
    float yp = __shfl_up_sync(0xffffffffu, Y, 1);
    if (lane == 0) yp = carry;
    if (tid == 0)  yp = 0.f;

    #pragma unroll 8
    for (int k = 0; k < LCH; k++) { yp = fmaf(m, yp, sc * x[k]); x[k] = yp; }
    __syncthreads();
}

// ---------------------------------------------------------------------------
// Fused kernel: one block per batch (R7, unchanged except d_A2 setup).
// ---------------------------------------------------------------------------
__global__ void fused_kernel(const float* __restrict__ exc,
                             const float* __restrict__ pitch,
                             const float* __restrict__ w1,
                             const float* __restrict__ b1,
                             const float* __restrict__ w2,
                             const float* __restrict__ b2,
                             const float* __restrict__ egain,
                             float* out_tail, int write_scalars)
{
    extern __shared__ float sm[];
    float* sig  = sm;              // [SIGSZ] skewed
    float* buf  = sm + SIGSZ;      // [KSL]
    float* scan = buf + KSL;       // [NTH]

    __shared__ float s_mpre, s_scpre, s_mpost, s_scpost;
    __shared__ float s_ser[5], s_fc[3];
    __shared__ int   s_L, s_Di, s_lag, s_Cb, s_nwT;
    __shared__ float s_lc[BATCH], s_lm[BATCH], s_lp[BATCH];

    int b = blockIdx.x, tid = threadIdx.x;

    if (tid == 0) {
        float p = pitch[b];
        float lc, lm, lp;
        mlp_eval(p, w1, b1, w2, b2, lc, lm, lp);

        float g = 0.999f * sigm(lc);
        float s = sigm(lm);
        float gs  = g * s;
        float g1s = g * (1.f - s);

        float f0    = fmaxf(p, 60.f);
        float mult  = clampf(2.f + 6.f * (f0 - 60.f) / 600.f, 2.f, 8.f);
        float cut   = fminf(2.f * PI_F * f0 * mult / FS_F, PI_F * 0.9f);
        float alpha = 1.f - expf(-cut);
        s_mpre  = 1.f - alpha;
        s_scpre = alpha * egain[0];

        float cutp = fminf(PI_F * sigm(lp), PI_F * 0.99f);
        float ap   = 1.f - expf(-cutp);
        s_mpost  = 1.f - ap;
        s_scpost = ap;

        float D  = clampf(FS_F / f0, 2.f, 735.f);
        float Df = floorf(D);
        int   Di = (int)Df;
        float fr = D - Df;
        s_Di = Di;

        float t1[3];
        t1[0] = g1s * (1.f - fr);
        t1[1] = g1s * fr + gs * (1.f - fr);
        t1[2] = gs * fr;

        if (Di - 2 >= 254) {
            s_L   = 0;
            s_lag = Di;
            s_Cb  = min(256, Di - 2);
            for (int k = 0; k < 3; k++) s_ser[k] = t1[k];
            s_ser[3] = 0.f; s_ser[4] = 0.f;
            s_fc[0] = s_fc[1] = s_fc[2] = 0.f;
        } else {
            // L = 1: (1 - C^2) y = (1 + C) x
            float t2[5];
            for (int k = 0; k < 5; k++) t2[k] = 0.f;
            for (int i = 0; i < 3; i++)
                for (int j = 0; j < 3; j++) t2[i + j] = fmaf(t1[i], t1[j], t2[i + j]);
            s_L   = 1;
            s_lag = 2 * Di;
            s_Cb  = min(256, 2 * Di);
            for (int k = 0; k < 5; k++) s_ser[k] = t2[k];
            for (int k = 0; k < 3; k++) s_fc[k]  = t1[k];
        }
        s_nwT = ((s_Cb + 31) >> 5) << 5;
    }

    if (b == 0) {
        if (tid >= 32 && tid < 32 + BATCH) {
            int bb = tid - 32;
            mlp_eval(pitch[bb], w1, b1, w2, b2, s_lc[bb], s_lm[bb], s_lp[bb]);
        }
        if (tid >= 64 && tid < 64 + NB) {
            int band = tid - 64;
            double fc  = 80.0 * exp(log(100.0) * (double)band / 23.0);
            float  fcf = (float)fc;
            float  w   = 2.f * PI_F * fcf / FS_F;
            float  r   = expf(-PI_F * fcf / (10.f * FS_F));
            float  a1  = -2.f * r * cosf(w);
            float  a2  = r * r;
            d_bA1[band] = a1; d_bA2[band] = a2; d_bB0[band] = 1.f - r;
            // A = [[-a1,-a2],[1,0]]; A^2 and level powers M^(128*2^j),
            // all in double (non-normal matrix powers cancel in float).
            double ma = -(double)a1, mb = -(double)a2, mc = 1.0, md = 0.0;
            {
                double na = ma * ma + mb * mc;
                double nb = ma * mb + mb * md;
                double nc = mc * ma + md * mc;
                double nd = mc * mb + md * md;
                d_A2[band][0] = (float)na; d_A2[band][1] = (float)nb;
                d_A2[band][2] = (float)nc; d_A2[band][3] = (float)nd;
            }
            for (int it = 0; it < 7; it++) {
                double na = ma * ma + mb * mc;
                double nb = ma * mb + mb * md;
                double nc = mc * ma + md * mc;
                double nd = mc * mb + md * md;
                ma = na; mb = nb; mc = nc; md = nd;
            }
            for (int j = 0; j < NLVL; j++) {
                d_Pl[band][j][0] = (float)ma; d_Pl[band][j][1] = (float)mb;
                d_Pl[band][j][2] = (float)mc; d_Pl[band][j][3] = (float)md;
                double na = ma * ma + mb * mc;
                double nb = ma * mb + mb * md;
                double nc = mc * ma + md * mc;
                double nd = mc * mb + md * md;
                ma = na; mb = nb; mc = nc; md = nd;
            }
        }
    }
    __syncthreads();

    if (b == 0 && tid == 0 && write_scalars) {
        float sc = 0.f, smm = 0.f, spp = 0.f;
        for (int i = 0; i < BATCH; i++) { sc += s_lc[i]; smm += s_lm[i]; spp += s_lp[i]; }
        out_tail[0] = sc  / (float)BATCH;
        out_tail[1] = smm / (float)BATCH;
        out_tail[2] = spp / (float)BATCH;
    }

    // load excitation (skewed) + zero KS ring
    const float* xin = exc + b * NSMP;
    for (int i = tid; i < NSMP; i += NTH) sig[SIDX(i)] = xin[i];
    for (int i = tid; i < KSL; i += NTH) buf[i] = 0.f;
    __syncthreads();

    // pre one-pole LP
    lp_inplace(sig, scan, s_mpre, s_scpre, tid);

    // ---------------- Karplus-Strong (R7, unchanged) ----------------
    {
        int Di = s_Di, lag = s_lag, Cb = s_Cb, nwT = s_nwT, L = s_L;
        float c0 = s_ser[0], c1 = s_ser[1], c2 = s_ser[2],
              c3 = s_ser[3], c4 = s_ser[4];
        float f0c = s_fc[0], f1c = s_fc[1], f2c = s_fc[2];

        if (L == 0) {
            if (tid < nwT) {
                for (int base = 0; base < NSMP; base += Cb) {
                    int n = base + tid;
                    if (tid < Cb && n < NSMP) {
                        float acc = sig[SIDX(n)];
                        acc = fmaf(c0, buf[(n - Di     + 2048) & (KSL - 1)], acc);
                        acc = fmaf(c1, buf[(n - Di - 1 + 2048) & (KSL - 1)], acc);
                        acc = fmaf(c2, buf[(n - Di - 2 + 2048) & (KSL - 1)], acc);
                        buf[n & (KSL - 1)] = acc;
                        sig[SIDX(n)] = acc;
                    }
                    asm volatile("bar.sync 1, %0;" :: "r"(nwT) : "memory");
                }
            }
        } else {
            if (tid < nwT) {
                float y0 = 0.f, y1v = 0.f;
                int rounds = (NSMP + Cb - 1) / Cb;
                int base = 0;
                for (int k = 0; k < rounds; k++, base += Cb) {
                    int n = base + tid;
                    float y = 0.f;
                    if (tid < Cb && n < NSMP) {
                        float acc = sig[SIDX(n)];
                        int i0 = n - Di, i1 = n - Di - 1, i2 = n - Di - 2;
                        float v0 = (i0 >= 0) ? sig[SIDX(i0)] : 0.f;
                        float v1 = (i1 >= 0) ? sig[SIDX(i1)] : 0.f;
                        float v2 = (i2 >= 0) ? sig[SIDX(i2)] : 0.f;
                        acc = fmaf(f0c, v0, acc);
                        acc = fmaf(f1c, v1, acc);
                        acc = fmaf(f2c, v2, acc);
                        int p = n - lag;
                        acc = fmaf(c0, buf[(p     + 2048) & (KSL - 1)], acc);
                        acc = fmaf(c1, buf[(p - 1 + 2048) & (KSL - 1)], acc);
                        acc = fmaf(c2, buf[(p - 2 + 2048) & (KSL - 1)], acc);
                        acc = fmaf(c3, buf[(p - 3 + 2048) & (KSL - 1)], acc);
                        acc = fmaf(c4, buf[(p - 4 + 2048) & (KSL - 1)], acc);
                        buf[n & (KSL - 1)] = acc;
                        y = acc;
                    }
                    int wb = base - 2 * Cb + tid;
                    if (tid < Cb && wb >= 0) sig[SIDX(wb)] = y0;
                    y0 = y1v; y1v = y;
                    asm volatile("bar.sync 1, %0;" :: "r"(nwT) : "memory");
                }
                for (int ff = 0; ff < 2; ff++, base += Cb) {
                    int wb = base - 2 * Cb + tid;
                    if (tid < Cb && wb >= 0 && wb < NSMP) sig[SIDX(wb)] = y0;
                    y0 = y1v; y1v = 0.f;
                }
            }
        }
        __syncthreads();
    }

    // post one-pole LP
    lp_inplace(sig, scan, s_mpost, s_scpost, tid);

    // write string out for the body stage (de-skew)
    float* yout = d_scr + b * NSMP;
    for (int i = tid; i < NSMP; i += NTH) yout[i] = sig[SIDX(i)];
}

// ---------------------------------------------------------------------------
// Body pass A: per (chunk, batch) 1-warp block, lane = band.
// A^2-doubled chain: s[2k+1] = A^2 s[2k-1] + b0(x[2k+1] u + x[2k] Au),
// 64 steps of 2 dependent FMAs instead of 128.
// ---------------------------------------------------------------------------
__global__ void bodyA_kernel()
{
    __shared__ float shx[BL];
    int b = blockIdx.y, c = blockIdx.x, tid = threadIdx.x;
    const float* x = d_scr + b * NSMP + c * BL;
    for (int i = tid; i < BL; i += 32) shx[i] = x[i];
    __syncthreads();
    if (tid < NB) {
        float a1 = d_bA1[tid], b0 = d_bB0[tid];
        float p00 = d_A2[tid][0], p01 = d_A2[tid][1];
        float p10 = d_A2[tid][2], p11 = d_A2[tid][3];
        float sx = 0.f, sy = 0.f;            // s[-1] = (y[-1], y[-2]) = 0
        #pragma unroll 8
        for (int k = 0; k < BL / 2; k++) {
            float x0 = shx[2 * k], x1 = shx[2 * k + 1];
            float wx = b0 * fmaf(-a1, x0, x1);
            float wy = b0 * x0;
            float nx = fmaf(p00, sx, fmaf(p01, sy, wx));
            float ny = fmaf(p10, sx, fmaf(p11, sy, wy));
            sx = nx; sy = ny;
        }
        d_carry[b][c][tid] = make_float2(sx, sy);  // (y[127], y[126])
    }
}

// ---------------------------------------------------------------------------
// Body pass B: parallel affine scan of chunk carries (unchanged).
// ---------------------------------------------------------------------------
__global__ void bodyB_kernel()
{
    __shared__ float2 s[BC];
    int band = blockIdx.x, b = blockIdx.y, c = threadIdx.x;
    float2 v = d_carry[b][c][band];
    s[c] = v;
    __syncthreads();
    #pragma unroll
    for (int j = 0; j < NLVL; j++) {
        int ofs = 1 << j;
        float q00 = d_Pl[band][j][0], q01 = d_Pl[band][j][1];
        float q10 = d_Pl[band][j][2], q11 = d_Pl[band][j][3];
        float2 pv = (c >= ofs) ? s[c - ofs] : make_float2(0.f, 0.f);
        __syncthreads();
        v.x = fmaf(q00, pv.x, fmaf(q01, pv.y, v.x));
        v.y = fmaf(q10, pv.x, fmaf(q11, pv.y, v.y));
        s[c] = v;
        __syncthreads();
    }
    d_initS[b][c][band] = (c > 0) ? s[c - 1] : make_float2(0.f, 0.f);
}

// ---------------------------------------------------------------------------
// Body pass C: A^2-doubled recompute (both y[2k], y[2k+1] live in the state),
// then weighted band sum.
// ---------------------------------------------------------------------------
__global__ void bodyC_kernel(const float* __restrict__ gains, float* __restrict__ out)
{
    __shared__ float shx[BL];
    __shared__ float tile[BL * 25];   // [t][band], stride 25 (pad)
    __shared__ float shg[NB];
    int b = blockIdx.y, c = blockIdx.x, tid = threadIdx.x;
    const float* x = d_scr + b * NSMP + c * BL;
    for (int i = tid; i < BL; i += 32) shx[i] = x[i];
    if (tid < NB) shg[tid] = gains[tid];
    __syncthreads();

    if (tid < NB) {
        float a1 = d_bA1[tid], b0 = d_bB0[tid];
        float p00 = d_A2[tid][0], p01 = d_A2[tid][1];
        float p10 = d_A2[tid][2], p11 = d_A2[tid][3];
        float2 s = d_initS[b][c][tid];
        float sx = s.x, sy = s.y;            // (y[-1], y[-2])
        #pragma unroll 8
        for (int k = 0; k < BL / 2; k++) {
            float x0 = shx[2 * k], x1 = shx[2 * k + 1];
            float wx = b0 * fmaf(-a1, x0, x1);
            float wy = b0 * x0;
            float nx = fmaf(p00, sx, fmaf(p01, sy, wx));
            float ny = fmaf(p10, sx, fmaf(p11, sy, wy));
            tile[(2 * k)     * 25 + tid] = ny;   // y[2k]
            tile[(2 * k + 1) * 25 + tid] = nx;   // y[2k+1]
            sx = nx; sy = ny;
        }
    }
    __syncthreads();

    for (int t = tid; t < BL; t += 32) {
        float acc = 0.f;
        #pragma unroll
        for (int k = 0; k < NB; k++) acc = fmaf(tile[t * 25 + k], shg[k], acc);
        out[b * NSMP + c * BL + t] = acc;
    }
}

// ---------------------------------------------------------------------------
extern "C" void kernel_launch(void* const* d_in, const int* in_sizes, int n_in,
                              void* d_out, int out_size)
{
    const float* exc   = (const float*)d_in[0];   // [8,1,32768]
    const float* pitch = (const float*)d_in[1];   // [8,1]
    const float* w1    = (const float*)d_in[2];   // [16,1]
    const float* b1    = (const float*)d_in[3];   // [16]
    const float* w2    = (const float*)d_in[4];   // [3,16]
    const float* b2    = (const float*)d_in[5];   // [3]
    const float* eg    = (const float*)d_in[6];   // scalar
    const float* bg    = (const float*)d_in[7];   // [1,24]
    float* out = (float*)d_out;

    int wr = (out_size >= BATCH * NSMP + 3) ? 1 : 0;

    const int smem_fused = (SIGSZ + KSL + NTH) * (int)sizeof(float);  // ~137 KB
    cudaFuncSetAttribute(fused_kernel,
                         cudaFuncAttributeMaxDynamicSharedMemorySize, smem_fused);

    fused_kernel<<<BATCH, NTH, smem_fused>>>(exc, pitch, w1, b1, w2, b2, eg,
                                             out + BATCH * NSMP, wr);
    bodyA_kernel<<<dim3(BC, BATCH), 32>>>();
    bodyB_kernel<<<dim3(NB, BATCH), BC>>>();
    bodyC_kernel<<<dim3(BC, BATCH), 32>>>(bg, out);
}